// round 12
// baseline (speedup 1.0000x reference)
#include <cuda_runtime.h>
#include <cstdint>

#define V_THRESHOLD 1.0f
#define EPS_CLIP 1e-8f

// ---------------------------------------------------------------------------
// Fused kernel, R12: identical to the converged R2 configuration EXCEPT the
// expmap blocks are scheduled FIRST (wave 1) so their MUFU/shfl latency
// overlaps the scan's DRAM saturation instead of forming a low-BW tail wave.
//   Blocks [0, exp_blocks)             : Lorentz expmap (one warp per row).
//   Blocks [exp_blocks, +scan_blocks)  : IF scan (thread owns one float4
//                                        column, scans T=16 in registers).
// Pure streaming -> evict-first (.cs) loads/stores.
// ---------------------------------------------------------------------------

__device__ __forceinline__ float4 ldcs4(const float4* p) {
    return __ldcs(p);
}
__device__ __forceinline__ void stcs4(float4* p, float4 v) {
    __stcs(p, v);
}

template <int T>
__device__ __forceinline__ void if_scan_body(
    const float4* __restrict__ x, float4* __restrict__ s,
    int i, int nd4)
{
    float4 mem = make_float4(0.f, 0.f, 0.f, 0.f);
#pragma unroll
    for (int t = 0; t < T; ++t) {
        size_t off = (size_t)t * nd4 + i;
        float4 xv = ldcs4(x + off);
        mem.x += xv.x; mem.y += xv.y; mem.z += xv.z; mem.w += xv.w;

        float4 sp;
        sp.x = mem.x > V_THRESHOLD ? 1.0f : 0.0f;
        sp.y = mem.y > V_THRESHOLD ? 1.0f : 0.0f;
        sp.z = mem.z > V_THRESHOLD ? 1.0f : 0.0f;
        sp.w = mem.w > V_THRESHOLD ? 1.0f : 0.0f;

        mem.x -= sp.x;  // V_THRESHOLD == 1.0f
        mem.y -= sp.y;
        mem.z -= sp.z;
        mem.w -= sp.w;

        stcs4(s + off, sp);
    }
}

__device__ __forceinline__ void expmap_body(
    const float4* __restrict__ v, const float4* __restrict__ z,
    float4* __restrict__ out, int row)
{
    int lane = threadIdx.x & 31;
    size_t base = (size_t)row * 64;

    float4 va = ldcs4(v + base + lane);
    float4 vb = ldcs4(v + base + lane + 32);

    float sum = va.x * va.x + va.y * va.y + va.z * va.z + va.w * va.w
              + vb.x * vb.x + vb.y * vb.y + vb.z * vb.z + vb.w * vb.w;
    if (lane == 0) sum -= 2.0f * va.x * va.x;   // Minkowski time component

#pragma unroll
    for (int o = 16; o > 0; o >>= 1)
        sum += __shfl_xor_sync(0xFFFFFFFFu, sum, o);

    float vn = sqrtf(fmaxf(sum, EPS_CLIP));
    float ch = coshf(vn);
    float sh = sinhf(vn) / vn;

    float4 za = ldcs4(z + base + lane);
    float4 zb = ldcs4(z + base + lane + 32);

    float4 oa, ob;
    oa.x = fmaf(ch, za.x, sh * va.x);
    oa.y = fmaf(ch, za.y, sh * va.y);
    oa.z = fmaf(ch, za.z, sh * va.z);
    oa.w = fmaf(ch, za.w, sh * va.w);
    ob.x = fmaf(ch, zb.x, sh * vb.x);
    ob.y = fmaf(ch, zb.y, sh * vb.y);
    ob.z = fmaf(ch, zb.z, sh * vb.z);
    ob.w = fmaf(ch, zb.w, sh * vb.w);

    stcs4(out + base + lane,      oa);
    stcs4(out + base + lane + 32, ob);
}

template <int T>
__global__ void __launch_bounds__(256) fused_kernel_ef(
    const float4* __restrict__ x,   // [T, ND/4]
    const float4* __restrict__ v,   // [N, 64]
    const float4* __restrict__ z,   // [N, 64]
    float4* __restrict__ s,         // [T, ND/4]
    float4* __restrict__ zout,      // [N, 64]
    int nd4, int N, int exp_blocks)
{
    if (blockIdx.x < (unsigned)exp_blocks) {
        int row = blockIdx.x * (blockDim.x >> 5) + (threadIdx.x >> 5);
        if (row < N) expmap_body(v, z, zout, row);
    } else {
        int i = (blockIdx.x - exp_blocks) * blockDim.x + threadIdx.x;
        if (i < nd4) if_scan_body<T>(x, s, i, nd4);
    }
}

// Dynamic-T fallback (T != 16), two separate plain kernels.
__global__ void __launch_bounds__(256) if_scan_dyn(
    const float4* __restrict__ x, float4* __restrict__ s, int nd4, int T)
{
    int i = blockIdx.x * blockDim.x + threadIdx.x;
    if (i >= nd4) return;
    float4 mem = make_float4(0.f, 0.f, 0.f, 0.f);
    for (int t = 0; t < T; ++t) {
        size_t off = (size_t)t * nd4 + i;
        float4 xv = __ldcs(x + off);
        mem.x += xv.x; mem.y += xv.y; mem.z += xv.z; mem.w += xv.w;
        float4 sp;
        sp.x = mem.x > V_THRESHOLD ? 1.0f : 0.0f;
        sp.y = mem.y > V_THRESHOLD ? 1.0f : 0.0f;
        sp.z = mem.z > V_THRESHOLD ? 1.0f : 0.0f;
        sp.w = mem.w > V_THRESHOLD ? 1.0f : 0.0f;
        mem.x -= V_THRESHOLD * sp.x;
        mem.y -= V_THRESHOLD * sp.y;
        mem.z -= V_THRESHOLD * sp.z;
        mem.w -= V_THRESHOLD * sp.w;
        __stcs(s + off, sp);
    }
}

__global__ void __launch_bounds__(256) expmap_only(
    const float4* __restrict__ v, const float4* __restrict__ z,
    float4* __restrict__ out, int N)
{
    int row = blockIdx.x * (blockDim.x >> 5) + (threadIdx.x >> 5);
    if (row < N) expmap_body(v, z, out, row);
}

// ---------------------------------------------------------------------------
// kernel_launch
//   d_in[0] = x_seq [T, N, D] fp32
//   d_in[1] = v_seq [N, D]    fp32
//   d_in[2] = z_seq [N, D]    fp32
//   d_out   = s_seq [T, N, D] fp32  followed by  z_out [N, D] fp32
// ---------------------------------------------------------------------------
extern "C" void kernel_launch(void* const* d_in, const int* in_sizes, int n_in,
                              void* d_out, int out_size)
{
    const float* x = (const float*)d_in[0];
    const float* v = (const float*)d_in[1];
    const float* z = (const float*)d_in[2];
    float* out = (float*)d_out;

    const int ND = in_sizes[1];            // N * D
    const int T  = in_sizes[0] / ND;       // 16
    const int D  = 256;
    const int N  = ND / D;

    float* s_out = out;                    // [T, N, D]
    float* z_out = out + (size_t)T * ND;   // [N, D]

    const int threads = 256;
    const int nd4 = ND / 4;
    const int scan_blocks = (nd4 + threads - 1) / threads;
    const int wpb = threads / 32;
    const int exp_blocks = (N + wpb - 1) / wpb;

    if (T == 16 && D == 256) {
        fused_kernel_ef<16><<<exp_blocks + scan_blocks, threads>>>(
            (const float4*)x, (const float4*)v, (const float4*)z,
            (float4*)s_out, (float4*)z_out, nd4, N, exp_blocks);
    } else {
        if_scan_dyn<<<scan_blocks, threads>>>(
            (const float4*)x, (float4*)s_out, nd4, T);
        expmap_only<<<exp_blocks, threads>>>(
            (const float4*)v, (const float4*)z, (float4*)z_out, N);
    }
}

// round 13
// speedup vs baseline: 1.0070x; 1.0070x over previous
#include <cuda_runtime.h>
#include <cstdint>

#define V_THRESHOLD 1.0f
#define EPS_CLIP 1e-8f

// ---------------------------------------------------------------------------
// CONVERGED FINAL (session optimum, reproduced 4x at 336.2-337.0 us bench).
//
//   Blocks [0, scan_blocks)            : IF scan (thread owns one float4
//                                        column, scans T=16 in registers).
//   Blocks [scan_blocks, scan_blocks+e): Lorentz expmap (one warp per row).
// Both halves are pure streaming -> evict-first (.cs) loads/stores.
//
// Perf model (validated): irreducible traffic = 2.338 GB, achieved HBM
// ~6.9 TB/s = B300 full-chip streaming ceiling (87% of 8 TB/s spec).
// dur = traffic / BW. All compute pipes <7%.
//
// Variants measured and rejected (bench us): 2 cols/thread 342.1,
// 512-thr blocks 338.0, 4-step bursts 338.5, persistent grid 348.8,
// v8(256-bit) scan 340.0, v8 scan+expmap 338.4, expmap-first 338.5.
// ---------------------------------------------------------------------------

__device__ __forceinline__ float4 ldcs4(const float4* p) {
    return __ldcs(p);
}
__device__ __forceinline__ void stcs4(float4* p, float4 v) {
    __stcs(p, v);
}

template <int T>
__device__ __forceinline__ void if_scan_body(
    const float4* __restrict__ x, float4* __restrict__ s,
    int i, int nd4)
{
    float4 mem = make_float4(0.f, 0.f, 0.f, 0.f);
#pragma unroll
    for (int t = 0; t < T; ++t) {
        size_t off = (size_t)t * nd4 + i;
        float4 xv = ldcs4(x + off);
        mem.x += xv.x; mem.y += xv.y; mem.z += xv.z; mem.w += xv.w;

        float4 sp;
        sp.x = mem.x > V_THRESHOLD ? 1.0f : 0.0f;
        sp.y = mem.y > V_THRESHOLD ? 1.0f : 0.0f;
        sp.z = mem.z > V_THRESHOLD ? 1.0f : 0.0f;
        sp.w = mem.w > V_THRESHOLD ? 1.0f : 0.0f;

        mem.x -= sp.x;  // V_THRESHOLD == 1.0f
        mem.y -= sp.y;
        mem.z -= sp.z;
        mem.w -= sp.w;

        stcs4(s + off, sp);
    }
}

__device__ __forceinline__ void expmap_body(
    const float4* __restrict__ v, const float4* __restrict__ z,
    float4* __restrict__ out, int row)
{
    int lane = threadIdx.x & 31;
    size_t base = (size_t)row * 64;

    float4 va = ldcs4(v + base + lane);
    float4 vb = ldcs4(v + base + lane + 32);

    float sum = va.x * va.x + va.y * va.y + va.z * va.z + va.w * va.w
              + vb.x * vb.x + vb.y * vb.y + vb.z * vb.z + vb.w * vb.w;
    if (lane == 0) sum -= 2.0f * va.x * va.x;   // Minkowski time component

#pragma unroll
    for (int o = 16; o > 0; o >>= 1)
        sum += __shfl_xor_sync(0xFFFFFFFFu, sum, o);

    float vn = sqrtf(fmaxf(sum, EPS_CLIP));
    float ch = coshf(vn);
    float sh = sinhf(vn) / vn;

    float4 za = ldcs4(z + base + lane);
    float4 zb = ldcs4(z + base + lane + 32);

    float4 oa, ob;
    oa.x = fmaf(ch, za.x, sh * va.x);
    oa.y = fmaf(ch, za.y, sh * va.y);
    oa.z = fmaf(ch, za.z, sh * va.z);
    oa.w = fmaf(ch, za.w, sh * va.w);
    ob.x = fmaf(ch, zb.x, sh * vb.x);
    ob.y = fmaf(ch, zb.y, sh * vb.y);
    ob.z = fmaf(ch, zb.z, sh * vb.z);
    ob.w = fmaf(ch, zb.w, sh * vb.w);

    stcs4(out + base + lane,      oa);
    stcs4(out + base + lane + 32, ob);
}

template <int T>
__global__ void __launch_bounds__(256) fused_kernel(
    const float4* __restrict__ x,   // [T, ND/4]
    const float4* __restrict__ v,   // [N, 64]
    const float4* __restrict__ z,   // [N, 64]
    float4* __restrict__ s,         // [T, ND/4]
    float4* __restrict__ zout,      // [N, 64]
    int nd4, int N, int scan_blocks)
{
    if (blockIdx.x < (unsigned)scan_blocks) {
        int i = blockIdx.x * blockDim.x + threadIdx.x;
        if (i < nd4) if_scan_body<T>(x, s, i, nd4);
    } else {
        int eb = blockIdx.x - scan_blocks;
        int row = eb * (blockDim.x >> 5) + (threadIdx.x >> 5);
        if (row < N) expmap_body(v, z, zout, row);
    }
}

// Dynamic-T fallback (T != 16), two separate plain kernels.
__global__ void __launch_bounds__(256) if_scan_dyn(
    const float4* __restrict__ x, float4* __restrict__ s, int nd4, int T)
{
    int i = blockIdx.x * blockDim.x + threadIdx.x;
    if (i >= nd4) return;
    float4 mem = make_float4(0.f, 0.f, 0.f, 0.f);
    for (int t = 0; t < T; ++t) {
        size_t off = (size_t)t * nd4 + i;
        float4 xv = __ldcs(x + off);
        mem.x += xv.x; mem.y += xv.y; mem.z += xv.z; mem.w += xv.w;
        float4 sp;
        sp.x = mem.x > V_THRESHOLD ? 1.0f : 0.0f;
        sp.y = mem.y > V_THRESHOLD ? 1.0f : 0.0f;
        sp.z = mem.z > V_THRESHOLD ? 1.0f : 0.0f;
        sp.w = mem.w > V_THRESHOLD ? 1.0f : 0.0f;
        mem.x -= V_THRESHOLD * sp.x;
        mem.y -= V_THRESHOLD * sp.y;
        mem.z -= V_THRESHOLD * sp.z;
        mem.w -= V_THRESHOLD * sp.w;
        __stcs(s + off, sp);
    }
}

__global__ void __launch_bounds__(256) expmap_only(
    const float4* __restrict__ v, const float4* __restrict__ z,
    float4* __restrict__ out, int N)
{
    int row = blockIdx.x * (blockDim.x >> 5) + (threadIdx.x >> 5);
    if (row < N) expmap_body(v, z, out, row);
}

// ---------------------------------------------------------------------------
// kernel_launch
//   d_in[0] = x_seq [T, N, D] fp32
//   d_in[1] = v_seq [N, D]    fp32
//   d_in[2] = z_seq [N, D]    fp32
//   d_out   = s_seq [T, N, D] fp32  followed by  z_out [N, D] fp32
// ---------------------------------------------------------------------------
extern "C" void kernel_launch(void* const* d_in, const int* in_sizes, int n_in,
                              void* d_out, int out_size)
{
    const float* x = (const float*)d_in[0];
    const float* v = (const float*)d_in[1];
    const float* z = (const float*)d_in[2];
    float* out = (float*)d_out;

    const int ND = in_sizes[1];            // N * D
    const int T  = in_sizes[0] / ND;       // 16
    const int D  = 256;
    const int N  = ND / D;

    float* s_out = out;                    // [T, N, D]
    float* z_out = out + (size_t)T * ND;   // [N, D]

    const int threads = 256;
    const int nd4 = ND / 4;
    const int scan_blocks = (nd4 + threads - 1) / threads;
    const int wpb = threads / 32;
    const int exp_blocks = (N + wpb - 1) / wpb;

    if (T == 16 && D == 256) {
        fused_kernel<16><<<scan_blocks + exp_blocks, threads>>>(
            (const float4*)x, (const float4*)v, (const float4*)z,
            (float4*)s_out, (float4*)z_out, nd4, N, scan_blocks);
    } else {
        if_scan_dyn<<<scan_blocks, threads>>>(
            (const float4*)x, (float4*)s_out, nd4, T);
        expmap_only<<<exp_blocks, threads>>>(
            (const float4*)v, (const float4*)z, (float4*)z_out, N);
    }
}